// round 1
// baseline (speedup 1.0000x reference)
#include <cuda_runtime.h>
#include <math.h>

#define NPTS 120000
#define NCH  128
#define HCH  64
#define TM   64
#define NBLK (NPTS / TM)   // 1875, exact
#define AS_LD 68           // padded A-tile stride (16B-aligned rows, bank-safe)

// Scratch (static device globals — no runtime allocation)
__device__ float g_a[(size_t)NPTS * NCH];
__device__ float g_b[(size_t)NPTS * NCH];
__device__ float g_t[(size_t)NPTS * HCH];
__device__ float g_u[(size_t)NPTS * HCH];

// ---------------------------------------------------------------------------
// Shared-memory staging helpers: 64x64 fp32 tiles, 256 threads, float4 loads
// ---------------------------------------------------------------------------
__device__ __forceinline__ void load_A64(const float* __restrict__ g, int ld,
                                         float* __restrict__ s) {
    int tid = threadIdx.x;
#pragma unroll
    for (int it = 0; it < 4; ++it) {
        int idx = tid + it * 256;        // 0..1023 float4 slots
        int row = idx >> 4;              // 16 float4 per 64-float row
        int c4  = (idx & 15) << 2;
        float4 v = *(const float4*)(g + (size_t)row * ld + c4);
        *(float4*)(s + row * AS_LD + c4) = v;
    }
}

__device__ __forceinline__ void load_W64(const float* __restrict__ g, int ld,
                                         float* __restrict__ s) {
    int tid = threadIdx.x;
#pragma unroll
    for (int it = 0; it < 4; ++it) {
        int idx = tid + it * 256;
        int row = idx >> 4;
        int c4  = (idx & 15) << 2;
        float4 v = *(const float4*)(g + (size_t)row * ld + c4);
        *(float4*)(s + row * 64 + c4) = v;
    }
}

// 64x64x64 fp32 micro-GEMM: acc[4][4] += A_tile @ W_tile
// thread (ty,tx): points ty*4..+4, cols tx*4..+4
__device__ __forceinline__ void mm64(const float* __restrict__ as,
                                     const float* __restrict__ ws,
                                     float acc[4][4], int ty, int tx) {
    const float* ap = as + ty * 4 * AS_LD;
    const float* wp = ws + tx * 4;
#pragma unroll 8
    for (int k = 0; k < 64; ++k) {
        float4 w = *(const float4*)(wp + k * 64);
        float a0 = ap[0 * AS_LD + k];
        float a1 = ap[1 * AS_LD + k];
        float a2 = ap[2 * AS_LD + k];
        float a3 = ap[3 * AS_LD + k];
        acc[0][0] += a0 * w.x; acc[0][1] += a0 * w.y; acc[0][2] += a0 * w.z; acc[0][3] += a0 * w.w;
        acc[1][0] += a1 * w.x; acc[1][1] += a1 * w.y; acc[1][2] += a1 * w.z; acc[1][3] += a1 * w.w;
        acc[2][0] += a2 * w.x; acc[2][1] += a2 * w.y; acc[2][2] += a2 * w.z; acc[2][3] += a2 * w.w;
        acc[3][0] += a3 * w.x; acc[3][1] += a3 * w.y; acc[3][2] += a3 * w.z; acc[3][3] += a3 * w.w;
    }
}

// ---------------------------------------------------------------------------
// fc1: g_t = relu(in @ W1), in: [NPTS,128] (x / g_a / g_b), W1: [128,64]
// ---------------------------------------------------------------------------
__global__ void __launch_bounds__(256)
fc1_kernel(const float* __restrict__ x, int insel, const float* __restrict__ W1) {
    __shared__ float as[TM * AS_LD];
    __shared__ float ws[64 * 64];
    const float* in = (insel == 0) ? x : (insel == 1 ? g_a : g_b);

    int p0 = blockIdx.x * TM;
    int tid = threadIdx.x, tx = tid & 15, ty = tid >> 4;
    float acc[4][4] = {};

#pragma unroll
    for (int ck = 0; ck < 2; ++ck) {
        load_A64(in + (size_t)p0 * NCH + ck * 64, NCH, as);
        load_W64(W1 + (size_t)ck * 64 * HCH, HCH, ws);
        __syncthreads();
        mm64(as, ws, acc, ty, tx);
        __syncthreads();
    }

#pragma unroll
    for (int i = 0; i < 4; ++i) {
        int p = p0 + ty * 4 + i;
        float4 v = make_float4(fmaxf(acc[i][0], 0.f), fmaxf(acc[i][1], 0.f),
                               fmaxf(acc[i][2], 0.f), fmaxf(acc[i][3], 0.f));
        *(float4*)(g_t + (size_t)p * HCH + tx * 4) = v;
    }
}

// ---------------------------------------------------------------------------
// conv3: g_u = relu( sum_{kk=0..26} gather(g_t, nbr[:,kk]) @ Wk[kk] )
// ---------------------------------------------------------------------------
__global__ void __launch_bounds__(256)
conv_kernel(const float* __restrict__ Wk, const int* __restrict__ nbr) {
    __shared__ float gs[TM * AS_LD];
    __shared__ float ws[64 * 64];

    int p0 = blockIdx.x * TM;
    int tid = threadIdx.x, tx = tid & 15, ty = tid >> 4;
    int lp = tid >> 2;               // point within tile (4 threads per point)
    int c0 = (tid & 3) * 16;         // 16 floats per thread
    float acc[4][4] = {};

    for (int kk = 0; kk < 27; ++kk) {
        load_W64(Wk + (size_t)kk * 64 * 64, 64, ws);
        int nb = nbr[(size_t)(p0 + lp) * 27 + kk];
        const float* src = g_t + (size_t)(nb < 0 ? 0 : nb) * HCH;
#pragma unroll
        for (int c = 0; c < 16; c += 4) {
            float4 v = make_float4(0.f, 0.f, 0.f, 0.f);
            if (nb >= 0) v = *(const float4*)(src + c0 + c);
            *(float4*)(gs + lp * AS_LD + c0 + c) = v;
        }
        __syncthreads();
        mm64(gs, ws, acc, ty, tx);
        __syncthreads();
    }

#pragma unroll
    for (int i = 0; i < 4; ++i) {
        int p = p0 + ty * 4 + i;
        float4 v = make_float4(fmaxf(acc[i][0], 0.f), fmaxf(acc[i][1], 0.f),
                               fmaxf(acc[i][2], 0.f), fmaxf(acc[i][3], 0.f));
        *(float4*)(g_u + (size_t)p * HCH + tx * 4) = v;
    }
}

// ---------------------------------------------------------------------------
// fc2: out = relu(g_u @ W2 + h); W2: [64,128]; grid.y = 2 column tiles
//      h/out selected: 0 -> x (read-only h only), 1 -> g_a, 2 -> g_b
// ---------------------------------------------------------------------------
__global__ void __launch_bounds__(256)
fc2_kernel(const float* __restrict__ x, const float* __restrict__ W2,
           int hsel, int outsel) {
    __shared__ float as[TM * AS_LD];
    __shared__ float ws[64 * 64];
    const float* h   = (hsel == 0) ? x : (hsel == 1 ? g_a : g_b);
    float*       out = (outsel == 1) ? g_a : g_b;

    int p0 = blockIdx.x * TM;
    int cb = blockIdx.y * 64;
    int tid = threadIdx.x, tx = tid & 15, ty = tid >> 4;
    float acc[4][4] = {};

    load_A64(g_u + (size_t)p0 * HCH, HCH, as);
    load_W64(W2 + cb, NCH, ws);
    __syncthreads();
    mm64(as, ws, acc, ty, tx);

#pragma unroll
    for (int i = 0; i < 4; ++i) {
        int p = p0 + ty * 4 + i;
        const float4 hv = *(const float4*)(h + (size_t)p * NCH + cb + tx * 4);
        float4 v = make_float4(fmaxf(acc[i][0] + hv.x, 0.f),
                               fmaxf(acc[i][1] + hv.y, 0.f),
                               fmaxf(acc[i][2] + hv.z, 0.f),
                               fmaxf(acc[i][3] + hv.w, 0.f));
        *(float4*)(out + (size_t)p * NCH + cb + tx * 4) = v;
    }
}

// ---------------------------------------------------------------------------
// final: out = g_a * sigmoid(g_b @ Wf) + x ; Wf: [128,128]; grid.y = 2
// ---------------------------------------------------------------------------
__global__ void __launch_bounds__(256)
final_kernel(const float* __restrict__ x, const float* __restrict__ Wf,
             float* __restrict__ out) {
    __shared__ float as[TM * AS_LD];
    __shared__ float ws[64 * 64];

    int p0 = blockIdx.x * TM;
    int cb = blockIdx.y * 64;
    int tid = threadIdx.x, tx = tid & 15, ty = tid >> 4;
    float acc[4][4] = {};

#pragma unroll
    for (int ck = 0; ck < 2; ++ck) {
        load_A64(g_b + (size_t)p0 * NCH + ck * 64, NCH, as);
        load_W64(Wf + (size_t)(ck * 64) * NCH + cb, NCH, ws);
        __syncthreads();
        mm64(as, ws, acc, ty, tx);
        __syncthreads();
    }

#pragma unroll
    for (int i = 0; i < 4; ++i) {
        int p = p0 + ty * 4 + i;
        size_t idx = (size_t)p * NCH + cb + tx * 4;
        const float4 av = *(const float4*)(g_a + idx);
        const float4 xv = *(const float4*)(x + idx);
        float4 v;
        v.x = av.x * (1.f / (1.f + expf(-acc[i][0]))) + xv.x;
        v.y = av.y * (1.f / (1.f + expf(-acc[i][1]))) + xv.y;
        v.z = av.z * (1.f / (1.f + expf(-acc[i][2]))) + xv.z;
        v.w = av.w * (1.f / (1.f + expf(-acc[i][3]))) + xv.w;
        *(float4*)(out + idx) = v;
    }
}

// ---------------------------------------------------------------------------
// Launch: 2 branches x 3 residual units, then gated merge
// Inputs (metadata order): x, W1s(6,128,64), Wks(6,27,64,64), W2s(6,64,128),
//                          Wf(128,128), nbr_idx(NPTS,27) int32
// ---------------------------------------------------------------------------
extern "C" void kernel_launch(void* const* d_in, const int* in_sizes, int n_in,
                              void* d_out, int out_size) {
    const float* x   = (const float*)d_in[0];
    const float* W1s = (const float*)d_in[1];
    const float* Wks = (const float*)d_in[2];
    const float* W2s = (const float*)d_in[3];
    const float* Wf  = (const float*)d_in[4];
    const int*   nbr = (const int*)d_in[5];
    float*       out = (float*)d_out;

    dim3 g1(NBLK), g2(NBLK, 2), blk(256);

    // branch a (units 0..2), accumulator g_a (sel 1)
    for (int i = 0; i < 3; ++i) {
        int hsel = (i == 0) ? 0 : 1;
        fc1_kernel<<<g1, blk>>>(x, hsel, W1s + (size_t)i * NCH * HCH);
        conv_kernel<<<g1, blk>>>(Wks + (size_t)i * 27 * HCH * HCH, nbr);
        fc2_kernel<<<g2, blk>>>(x, W2s + (size_t)i * HCH * NCH, hsel, 1);
    }
    // branch b (units 3..5), accumulator g_b (sel 2)
    for (int i = 3; i < 6; ++i) {
        int hsel = (i == 3) ? 0 : 2;
        fc1_kernel<<<g1, blk>>>(x, hsel, W1s + (size_t)i * NCH * HCH);
        conv_kernel<<<g1, blk>>>(Wks + (size_t)i * 27 * HCH * HCH, nbr);
        fc2_kernel<<<g2, blk>>>(x, W2s + (size_t)i * HCH * NCH, hsel, 2);
    }
    final_kernel<<<g2, blk>>>(x, Wf, out);
}